// round 10
// baseline (speedup 1.0000x reference)
#include <cuda_runtime.h>
#include <cstdint>

// Problem constants (fixed by setup_inputs)
#define B_  64
#define NO_ 1024
#define NI_ 1024
#define NBT 8          // batches per block

// RHO_R = exp(-DT/TAU_R) = exp(-0.05)
__device__ __constant__ float kRhoR = 0.95122942450071400910f;

// Multi-wave grid (wall-optimal family: R3). Block = (j, 8-batch tile),
// 256 threads x float4 = 1024 = NI.
// Three-phase body with in-place register reuse:
//   1) 8 streaming float4 loads (read burst, MLP=8)
//   2) 8 FMAs overwriting hv[] in place (+ partial sums) -- no reg growth
//   3) 8 streaming stores as one contiguous write burst
// Groups same-direction DRAM traffic per warp to cut bus turnarounds.
__global__ void __launch_bounds__(256)
hetsyn_cell_kernel(const float* __restrict__ x,      // (B, NI)
                   const float* __restrict__ w,      // (NO, NI)
                   const float* __restrict__ rho,    // (NO, NI)
                   const float* __restrict__ hz,     // (B, NO)
                   const float* __restrict__ hIsyn,  // (B, NO, NI)
                   const float* __restrict__ hIr,    // (B, NO)
                   float* __restrict__ z_out,        // (B, NO)
                   float* __restrict__ Isyn_out,     // (B, NO, NI)
                   float* __restrict__ Ir_out)       // (B, NO)
{
    const int j  = blockIdx.x;          // output neuron row
    const int b0 = blockIdx.y * NBT;    // first batch of this tile
    const int t  = threadIdx.x;         // 0..255

    const size_t wrow = (size_t)j * NI_;
    const float4 rv = __ldg(reinterpret_cast<const float4*>(rho + wrow) + t);
    const float4 wv = __ldg(reinterpret_cast<const float4*>(w   + wrow) + t);

    const size_t row0 = ((size_t)b0 * NO_ + j) * (size_t)NI_;

    // ---- Phase 1: read burst (8 streaming loads in flight) ----
    float4 hv[NBT];
    {
        const float4* p = reinterpret_cast<const float4*>(hIsyn + row0) + t;
        #pragma unroll
        for (int bb = 0; bb < NBT; ++bb) {
            hv[bb] = __ldcs(p);
            p += (size_t)NO_ * NI_ / 4;
        }
    }

    // ---- Phase 2: FMAs in place + partial sums (x is L2-resident) ----
    float psum[NBT];
    #pragma unroll
    for (int bb = 0; bb < NBT; ++bb) {
        const float4 xv = __ldg(reinterpret_cast<const float4*>(
            x + (size_t)(b0 + bb) * NI_) + t);

        hv[bb].x = fmaf(rv.x, hv[bb].x, wv.x * xv.x);
        hv[bb].y = fmaf(rv.y, hv[bb].y, wv.y * xv.y);
        hv[bb].z = fmaf(rv.z, hv[bb].z, wv.z * xv.z);
        hv[bb].w = fmaf(rv.w, hv[bb].w, wv.w * xv.w);

        psum[bb] = (hv[bb].x + hv[bb].y) + (hv[bb].z + hv[bb].w);
    }

    // ---- Phase 3: write burst (8 streaming stores back-to-back) ----
    {
        float4* q = reinterpret_cast<float4*>(Isyn_out + row0) + t;
        #pragma unroll
        for (int bb = 0; bb < NBT; ++bb) {
            __stcs(q, hv[bb]);
            q += (size_t)NO_ * NI_ / 4;
        }
    }

    // ---- Row-sum reduction per batch ----
    #pragma unroll
    for (int bb = 0; bb < NBT; ++bb) {
        #pragma unroll
        for (int off = 16; off > 0; off >>= 1)
            psum[bb] += __shfl_down_sync(0xFFFFFFFFu, psum[bb], off);
    }

    __shared__ float wsum[8][NBT];   // [warp][batch]
    const int lane = t & 31;
    const int warp = t >> 5;
    if (lane == 0) {
        #pragma unroll
        for (int bb = 0; bb < NBT; ++bb) wsum[warp][bb] = psum[bb];
    }
    __syncthreads();

    if (t < NBT) {
        float v_in = 0.0f;
        #pragma unroll
        for (int k = 0; k < 8; ++k) v_in += wsum[k][t];

        const int oidx = (b0 + t) * NO_ + j;
        const float Ir = fmaf(kRhoR, hIr[oidx], hz[oidx]);
        Ir_out[oidx] = Ir;
        // v = v_in - THR*Ir; z = (v - THR >= 0), THR = 1
        z_out[oidx]  = (v_in - Ir - 1.0f >= 0.0f) ? 1.0f : 0.0f;
    }
}

extern "C" void kernel_launch(void* const* d_in, const int* in_sizes, int n_in,
                              void* d_out, int out_size)
{
    // Input order per setup_inputs: x, w, rho, hz, hIsyn, hIr
    const float* x     = (const float*)d_in[0];
    const float* w     = (const float*)d_in[1];
    const float* rho   = (const float*)d_in[2];
    const float* hz    = (const float*)d_in[3];
    const float* hIsyn = (const float*)d_in[4];
    const float* hIr   = (const float*)d_in[5];

    // Output tuple (z, Isyn, Ir) flattened + concatenated
    float* out    = (float*)d_out;
    float* z_out  = out;
    float* Isyn_o = out + (size_t)B_ * NO_;
    float* Ir_out = out + (size_t)B_ * NO_ + (size_t)B_ * NO_ * NI_;

    dim3 grid(NO_, B_ / NBT);   // (1024, 8) = 8192 blocks, multi-wave
    dim3 block(256);
    hetsyn_cell_kernel<<<grid, block>>>(x, w, rho, hz, hIsyn, hIr,
                                        z_out, Isyn_o, Ir_out);
}

// round 11
// speedup vs baseline: 1.1052x; 1.1052x over previous
#include <cuda_runtime.h>
#include <cstdint>

// Problem constants (fixed by setup_inputs)
#define B_  64
#define NO_ 1024
#define NI_ 1024
#define NBT 8                          // batches per block
#define BSTRIDE (NO_ * NI_)            // elements between consecutive batches

// RHO_R = exp(-DT/TAU_R) = exp(-0.05)
__device__ __constant__ float kRhoR = 0.95122942450071400910f;

// R3 structure (wall-optimal across 10 measured variants).
// Block = (j, 8-batch tile), 256 threads x float4 = 1024 = NI.
//   Phase 1: 8 streaming float4 loads, front-batched, base+IMMEDIATE offsets
//            (bb*4MB fits LDG's +/-8MB immediate field -> no IADD chain).
//   Phase 2: interleaved ldg(x) -> FMA -> stcs(Isyn) per batch (stores ramp
//            while later reads are still in flight).
//   Then per-batch row reduction + neuron update.
__global__ void __launch_bounds__(256, 4)
hetsyn_cell_kernel(const float* __restrict__ x,      // (B, NI)
                   const float* __restrict__ w,      // (NO, NI)
                   const float* __restrict__ rho,    // (NO, NI)
                   const float* __restrict__ hz,     // (B, NO)
                   const float* __restrict__ hIsyn,  // (B, NO, NI)
                   const float* __restrict__ hIr,    // (B, NO)
                   float* __restrict__ z_out,        // (B, NO)
                   float* __restrict__ Isyn_out,     // (B, NO, NI)
                   float* __restrict__ Ir_out)       // (B, NO)
{
    const int j  = blockIdx.x;          // output neuron row
    const int b0 = blockIdx.y * NBT;    // first batch of this tile
    const int t  = threadIdx.x;         // 0..255

    // rho/w row: L2-resident (8 MB working set), loaded before streams start
    const float4* rbase = reinterpret_cast<const float4*>(rho) + ((size_t)j << 8) + t;
    const float4* wbase = reinterpret_cast<const float4*>(w)   + ((size_t)j << 8) + t;
    const float4 rv = __ldg(rbase);
    const float4 wv = __ldg(wbase);

    // Single base pointer; batch offsets are compile-time immediates.
    const size_t row0 = ((size_t)(b0 * NO_ + j) << 10);
    const float4* hbase = reinterpret_cast<const float4*>(hIsyn)    + (row0 >> 2) + t;
    float4*       qbase = reinterpret_cast<float4*>(Isyn_out)       + (row0 >> 2) + t;
    const float4* xbase = reinterpret_cast<const float4*>(x) + ((size_t)b0 << 8) + t;

    // ---- Phase 1: front-batch all 8 streaming loads (MLP=8) ----
    float4 hv[NBT];
    #pragma unroll
    for (int bb = 0; bb < NBT; ++bb)
        hv[bb] = __ldcs(hbase + (size_t)bb * (BSTRIDE / 4));

    // ---- Phase 2: interleaved compute + streaming store per batch ----
    float psum[NBT];
    #pragma unroll
    for (int bb = 0; bb < NBT; ++bb) {
        const float4 xv = __ldg(xbase + (size_t)bb * (NI_ / 4));

        float4 Is;
        Is.x = fmaf(rv.x, hv[bb].x, wv.x * xv.x);
        Is.y = fmaf(rv.y, hv[bb].y, wv.y * xv.y);
        Is.z = fmaf(rv.z, hv[bb].z, wv.z * xv.z);
        Is.w = fmaf(rv.w, hv[bb].w, wv.w * xv.w);

        __stcs(qbase + (size_t)bb * (BSTRIDE / 4), Is);

        psum[bb] = (Is.x + Is.y) + (Is.z + Is.w);
    }

    // ---- Row-sum reduction per batch ----
    #pragma unroll
    for (int bb = 0; bb < NBT; ++bb) {
        #pragma unroll
        for (int off = 16; off > 0; off >>= 1)
            psum[bb] += __shfl_down_sync(0xFFFFFFFFu, psum[bb], off);
    }

    __shared__ float wsum[8][NBT];   // [warp][batch]
    const int lane = t & 31;
    const int warp = t >> 5;
    if (lane == 0) {
        #pragma unroll
        for (int bb = 0; bb < NBT; ++bb) wsum[warp][bb] = psum[bb];
    }
    __syncthreads();

    if (t < NBT) {
        float v_in = 0.0f;
        #pragma unroll
        for (int k = 0; k < 8; ++k) v_in += wsum[k][t];

        const int oidx = (b0 + t) * NO_ + j;
        const float Ir = fmaf(kRhoR, hIr[oidx], hz[oidx]);
        Ir_out[oidx] = Ir;
        // v = v_in - THR*Ir; z = (v - THR >= 0), THR = 1
        z_out[oidx]  = (v_in - Ir - 1.0f >= 0.0f) ? 1.0f : 0.0f;
    }
}

extern "C" void kernel_launch(void* const* d_in, const int* in_sizes, int n_in,
                              void* d_out, int out_size)
{
    // Input order per setup_inputs: x, w, rho, hz, hIsyn, hIr
    const float* x     = (const float*)d_in[0];
    const float* w     = (const float*)d_in[1];
    const float* rho   = (const float*)d_in[2];
    const float* hz    = (const float*)d_in[3];
    const float* hIsyn = (const float*)d_in[4];
    const float* hIr   = (const float*)d_in[5];

    // Output tuple (z, Isyn, Ir) flattened + concatenated
    float* out    = (float*)d_out;
    float* z_out  = out;
    float* Isyn_o = out + (size_t)B_ * NO_;
    float* Ir_out = out + (size_t)B_ * NO_ + (size_t)B_ * NO_ * NI_;

    dim3 grid(NO_, B_ / NBT);   // (1024, 8) = 8192 blocks, multi-wave
    dim3 block(256);
    hetsyn_cell_kernel<<<grid, block>>>(x, w, rho, hz, hIsyn, hIr,
                                        z_out, Isyn_o, Ir_out);
}